// round 5
// baseline (speedup 1.0000x reference)
#include <cuda_runtime.h>
#include <cstdint>

// e4m3 fake-quantize: out = Q(x * (1/s)) * s
//   Q(y): e = max(floor(log2|y|), -6); lsb = 2^(e-3);
//         q = min(rne(|y| * 2^(3-e)) * lsb, 240); sign-restore.
// Division-free, exact (rel_err 0.0 vs reference).
// HBM-wall streaming: 16x float4/thread, fully front-batched loads then a
// contiguous store burst (longer homogeneous DRAM bursts -> fewer R/W
// turnarounds), __ldcs/__stcs, zero predicates + u32 byte offsets on the
// exactly-divisible path.

__device__ __forceinline__ float fq_e4m3(float x, float s_inv, float s) {
    float y = x * s_inv;
    float ay = fabsf(y);
    int e = ((__float_as_int(ay) >> 23) & 0xFF) - 127;   // floor(log2|y|), exact
    e = max(e, -6);
    float lsb     = __int_as_float((e - 3 + 127) << 23); // 2^(e-3), exact
    float inv_lsb = __int_as_float((3 - e + 127) << 23); // 2^(3-e), exact
    float q = rintf(ay * inv_lsb) * lsb;  // RN => round-half-even (matches jnp.round)
    q = fminf(q, 240.0f);
    return copysignf(q, y) * s;
}

__device__ __forceinline__ float4 fq4(float4 v, float s_inv, float s) {
    float4 r;
    r.x = fq_e4m3(v.x, s_inv, s);
    r.y = fq_e4m3(v.y, s_inv, s);
    r.z = fq_e4m3(v.z, s_inv, s);
    r.w = fq_e4m3(v.w, s_inv, s);
    return r;
}

#define VPT 16  // float4s per thread
#define TPB 256

// Exact path: n4 % (TPB*VPT) == 0 and total bytes < 2^31.
__global__ void __launch_bounds__(TPB) fq_exact16(const char* __restrict__ xb,
                                                  const float* __restrict__ scale,
                                                  char* __restrict__ ob) {
    unsigned base = (blockIdx.x * (TPB * VPT) + threadIdx.x) * 16u;

    float s = __ldg(scale);
    float s_inv = 1.0f / s;

    float4 v[VPT];
#pragma unroll
    for (int j = 0; j < VPT; j++)
        v[j] = __ldcs((const float4*)(xb + base + j * (TPB * 16u)));
#pragma unroll
    for (int j = 0; j < VPT; j++)
        v[j] = fq4(v[j], s_inv, s);
#pragma unroll
    for (int j = 0; j < VPT; j++)
        __stcs((float4*)(ob + base + j * (TPB * 16u)), v[j]);
}

// Generic fallback (any n multiple of 4).
__global__ void __launch_bounds__(TPB) fq_generic(const float4* __restrict__ x,
                                                  const float* __restrict__ scale,
                                                  float4* __restrict__ out,
                                                  long long n4) {
    long long base = (long long)blockIdx.x * (TPB * 8) + threadIdx.x;
    float s = __ldg(scale);
    float s_inv = 1.0f / s;
#pragma unroll
    for (int j = 0; j < 8; j++) {
        long long i = base + (long long)j * TPB;
        if (i < n4) __stcs(&out[i], fq4(__ldcs(&x[i]), s_inv, s));
    }
}

// Scalar tail for non-multiple-of-4 element counts.
__global__ void fq_tail(const float* __restrict__ x, const float* __restrict__ scale,
                        float* __restrict__ out, long long start, long long n) {
    long long i = start + blockIdx.x * blockDim.x + threadIdx.x;
    if (i >= n) return;
    float s = __ldg(scale);
    out[i] = fq_e4m3(x[i], 1.0f / s, s);
}

extern "C" void kernel_launch(void* const* d_in, const int* in_sizes, int n_in,
                              void* d_out, int out_size) {
    const float* x = (const float*)d_in[0];
    const float* scale = (const float*)d_in[1];
    float* out = (float*)d_out;
    long long n = (long long)in_sizes[0];

    long long n4 = n >> 2;
    const long long per_block = (long long)TPB * VPT;

    if (n4 > 0 && (n4 % per_block) == 0 && n * 4ll < (1ll << 31)) {
        unsigned blocks = (unsigned)(n4 / per_block);
        fq_exact16<<<blocks, TPB>>>((const char*)x, scale, (char*)out);
    } else if (n4 > 0) {
        const long long pb8 = (long long)TPB * 8;
        long long blocks = (n4 + pb8 - 1) / pb8;
        fq_generic<<<(unsigned)blocks, TPB>>>((const float4*)x, scale, (float4*)out, n4);
    }
    long long done = n4 << 2;
    if (done < n) {
        long long rem = n - done;
        fq_tail<<<(unsigned)((rem + 255) / 256), 256>>>(x, scale, out, done, n);
    }
}

// round 6
// speedup vs baseline: 1.0045x; 1.0045x over previous
#include <cuda_runtime.h>
#include <cstdint>

// e4m3 fake-quantize: out = Q(x * (1/s)) * s
//   Q(y): e = max(floor(log2|y|), -6); lsb = 2^(e-3);
//         q = min(rne(|y| * 2^(3-e)) * lsb, 240); sign-restore.
// Division-free, exact (rel_err 0.0 vs reference).
//
// FINAL (converged at the HBM wall): 8x float4/thread front-batched (MLP=8),
// __ldcs/__stcs streaming hints, zero predicates + u32 byte-offset addressing
// on the exactly-divisible path. Measured 6.84 TB/s (86.3% of spec) for a
// 1:1 read/write stream; VPT sweep {4,8,16} brackets 8 as the optimum
// (16 loses concurrency: occ 32%, DRAM 83.9%; 4 loses latency cover).

__device__ __forceinline__ float fq_e4m3(float x, float s_inv, float s) {
    float y = x * s_inv;
    float ay = fabsf(y);
    int e = ((__float_as_int(ay) >> 23) & 0xFF) - 127;   // floor(log2|y|), exact
    e = max(e, -6);
    float lsb     = __int_as_float((e - 3 + 127) << 23); // 2^(e-3), exact
    float inv_lsb = __int_as_float((3 - e + 127) << 23); // 2^(3-e), exact
    float q = rintf(ay * inv_lsb) * lsb;  // RN => round-half-even (matches jnp.round)
    q = fminf(q, 240.0f);
    return copysignf(q, y) * s;
}

__device__ __forceinline__ float4 fq4(float4 v, float s_inv, float s) {
    float4 r;
    r.x = fq_e4m3(v.x, s_inv, s);
    r.y = fq_e4m3(v.y, s_inv, s);
    r.z = fq_e4m3(v.z, s_inv, s);
    r.w = fq_e4m3(v.w, s_inv, s);
    return r;
}

#define VPT 8   // float4s per thread (measured optimum)
#define TPB 256

// Exact path: n4 % (TPB*VPT) == 0 and total bytes < 2^31. No predicates,
// u32 byte-offset addressing (single IMAD per access).
__global__ void __launch_bounds__(TPB) fq_exact(const char* __restrict__ xb,
                                                const float* __restrict__ scale,
                                                char* __restrict__ ob) {
    unsigned base = (blockIdx.x * (TPB * VPT) + threadIdx.x) * 16u;

    float s = __ldg(scale);
    float s_inv = 1.0f / s;

    float4 v[VPT];
#pragma unroll
    for (int j = 0; j < VPT; j++)
        v[j] = __ldcs((const float4*)(xb + base + j * (TPB * 16u)));
#pragma unroll
    for (int j = 0; j < VPT; j++)
        __stcs((float4*)(ob + base + j * (TPB * 16u)), fq4(v[j], s_inv, s));
}

// Generic fallback (any n multiple of 4).
__global__ void __launch_bounds__(TPB) fq_generic(const float4* __restrict__ x,
                                                  const float* __restrict__ scale,
                                                  float4* __restrict__ out,
                                                  long long n4) {
    long long base = (long long)blockIdx.x * (TPB * VPT) + threadIdx.x;
    float s = __ldg(scale);
    float s_inv = 1.0f / s;
#pragma unroll
    for (int j = 0; j < VPT; j++) {
        long long i = base + (long long)j * TPB;
        if (i < n4) __stcs(&out[i], fq4(__ldcs(&x[i]), s_inv, s));
    }
}

// Scalar tail for non-multiple-of-4 element counts.
__global__ void fq_tail(const float* __restrict__ x, const float* __restrict__ scale,
                        float* __restrict__ out, long long start, long long n) {
    long long i = start + blockIdx.x * blockDim.x + threadIdx.x;
    if (i >= n) return;
    float s = __ldg(scale);
    out[i] = fq_e4m3(x[i], 1.0f / s, s);
}

extern "C" void kernel_launch(void* const* d_in, const int* in_sizes, int n_in,
                              void* d_out, int out_size) {
    const float* x = (const float*)d_in[0];
    const float* scale = (const float*)d_in[1];
    float* out = (float*)d_out;
    long long n = (long long)in_sizes[0];

    long long n4 = n >> 2;
    const long long per_block = (long long)TPB * VPT;

    if (n4 > 0 && (n4 % per_block) == 0 && n * 4ll < (1ll << 31)) {
        unsigned blocks = (unsigned)(n4 / per_block);
        fq_exact<<<blocks, TPB>>>((const char*)x, scale, (char*)out);
    } else if (n4 > 0) {
        long long blocks = (n4 + per_block - 1) / per_block;
        fq_generic<<<(unsigned)blocks, TPB>>>((const float4*)x, scale, (float4*)out, n4);
    }
    long long done = n4 << 2;
    if (done < n) {
        long long rem = n - done;
        fq_tail<<<(unsigned)((rem + 255) / 256), 256>>>(x, scale, out, done, n);
    }
}

// round 7
// speedup vs baseline: 1.0121x; 1.0076x over previous
#include <cuda_runtime.h>
#include <cstdint>

// e4m3 fake-quantize: out = Q(x * (1/s)) * s
//   Q(y): e = max(floor(log2|y|), -6); lsb = 2^(e-3);
//         q = min(rne(|y| * 2^(3-e)) * lsb, 240); sign-restore.
// Division-free, exact (rel_err 0.0 vs reference).
//
// HBM-wall streaming kernel. Final bracket: TPB=128 (grid 32768, more
// independent request streams), loads with .lu (last-use: release L2 lines
// immediately), stores with .cs. 8x float4/thread front-batched (MLP=8),
// zero predicates + u32 byte offsets on the exactly-divisible path.

__device__ __forceinline__ float fq_e4m3(float x, float s_inv, float s) {
    float y = x * s_inv;
    float ay = fabsf(y);
    int e = ((__float_as_int(ay) >> 23) & 0xFF) - 127;   // floor(log2|y|), exact
    e = max(e, -6);
    float lsb     = __int_as_float((e - 3 + 127) << 23); // 2^(e-3), exact
    float inv_lsb = __int_as_float((3 - e + 127) << 23); // 2^(3-e), exact
    float q = rintf(ay * inv_lsb) * lsb;  // RN => round-half-even (matches jnp.round)
    q = fminf(q, 240.0f);
    return copysignf(q, y) * s;
}

__device__ __forceinline__ float4 fq4(float4 v, float s_inv, float s) {
    float4 r;
    r.x = fq_e4m3(v.x, s_inv, s);
    r.y = fq_e4m3(v.y, s_inv, s);
    r.z = fq_e4m3(v.z, s_inv, s);
    r.w = fq_e4m3(v.w, s_inv, s);
    return r;
}

#define VPT 8   // float4s per thread
#define TPB 128

// Exact path: n4 % (TPB*VPT) == 0 and total bytes < 2^31.
__global__ void __launch_bounds__(TPB) fq_exact(const char* __restrict__ xb,
                                                const float* __restrict__ scale,
                                                char* __restrict__ ob) {
    unsigned base = (blockIdx.x * (TPB * VPT) + threadIdx.x) * 16u;

    float s = __ldg(scale);
    float s_inv = 1.0f / s;

    float4 v[VPT];
#pragma unroll
    for (int j = 0; j < VPT; j++)
        v[j] = __ldlu((const float4*)(xb + base + j * (TPB * 16u)));
#pragma unroll
    for (int j = 0; j < VPT; j++)
        __stcs((float4*)(ob + base + j * (TPB * 16u)), fq4(v[j], s_inv, s));
}

// Generic fallback (any n multiple of 4).
__global__ void __launch_bounds__(TPB) fq_generic(const float4* __restrict__ x,
                                                  const float* __restrict__ scale,
                                                  float4* __restrict__ out,
                                                  long long n4) {
    long long base = (long long)blockIdx.x * (TPB * VPT) + threadIdx.x;
    float s = __ldg(scale);
    float s_inv = 1.0f / s;
#pragma unroll
    for (int j = 0; j < VPT; j++) {
        long long i = base + (long long)j * TPB;
        if (i < n4) __stcs(&out[i], fq4(__ldcs(&x[i]), s_inv, s));
    }
}

// Scalar tail for non-multiple-of-4 element counts.
__global__ void fq_tail(const float* __restrict__ x, const float* __restrict__ scale,
                        float* __restrict__ out, long long start, long long n) {
    long long i = start + blockIdx.x * blockDim.x + threadIdx.x;
    if (i >= n) return;
    float s = __ldg(scale);
    out[i] = fq_e4m3(x[i], 1.0f / s, s);
}

extern "C" void kernel_launch(void* const* d_in, const int* in_sizes, int n_in,
                              void* d_out, int out_size) {
    const float* x = (const float*)d_in[0];
    const float* scale = (const float*)d_in[1];
    float* out = (float*)d_out;
    long long n = (long long)in_sizes[0];

    long long n4 = n >> 2;
    const long long per_block = (long long)TPB * VPT;

    if (n4 > 0 && (n4 % per_block) == 0 && n * 4ll < (1ll << 31)) {
        unsigned blocks = (unsigned)(n4 / per_block);
        fq_exact<<<blocks, TPB>>>((const char*)x, scale, (char*)out);
    } else if (n4 > 0) {
        long long blocks = (n4 + per_block - 1) / per_block;
        fq_generic<<<(unsigned)blocks, TPB>>>((const float4*)x, scale, (float4*)out, n4);
    }
    long long done = n4 << 2;
    if (done < n) {
        long long rem = n - done;
        fq_tail<<<(unsigned)((rem + 255) / 256), 256>>>(x, scale, out, done, n);
    }
}